// round 3
// baseline (speedup 1.0000x reference)
#include <cuda_runtime.h>
#include <cuda_bf16.h>

#define NN 100000
#define EE 1600000

// ---------------- scratch (static device globals; no allocation) ----------------
__device__ __align__(16) float g_h0[NN * 64];
__device__ __align__(16) float g_xl[NN * 64];
__device__ __align__(16) float g_xr[NN * 64];
__device__ __align__(16) float g_wcat[128 * 192];
__device__ int   g_cnt[NN];
__device__ float g_sumw[NN];
__device__ int   g_fill[NN];
__device__ int   g_rowptr[NN + 1];
__device__ int2  g_csr[EE];
__device__ int   g_bsum[128];
__device__ int   g_boff[128];
__device__ int   g_is64;

// ---------------- dtype detection: int64 edge_index => odd 32-bit words are all 0 ----------------
__global__ void k_detect(const int* __restrict__ ei32) {
    if (threadIdx.x == 0 && blockIdx.x == 0) {
        int all0 = 1;
        #pragma unroll
        for (int j = 0; j < 8; j++)
            if (ei32[2 * j + 1] != 0) all0 = 0;
        g_is64 = all0;
    }
}

__device__ __forceinline__ int load_idx(const void* ei, int pos) {
    if (g_is64) return (int)((const long long*)ei)[pos];
    return ((const int*)ei)[pos];
}

// ---------------- init ----------------
__global__ void k_zero() {
    int i = blockIdx.x * blockDim.x + threadIdx.x;
    if (i < NN) { g_cnt[i] = 0; g_sumw[i] = 0.f; g_fill[i] = 0; }
}

// ---------------- composite weight: wcat = [W_pre | W_pre@W_l | W_pre@W_r] ----------------
__global__ void k_build_wcat(const float* __restrict__ W_pre,
                             const float* __restrict__ W_l,
                             const float* __restrict__ W_r) {
    int k = blockIdx.x;        // 0..127
    int j = threadIdx.x;       // 0..191
    float v;
    if (j < 64) {
        v = W_pre[k * 64 + j];
    } else {
        const float* W = (j < 128) ? W_l : W_r;
        int c = (j < 128) ? (j - 64) : (j - 128);
        float s = 0.f;
        #pragma unroll 8
        for (int m = 0; m < 64; m++) s += W_pre[k * 64 + m] * W[m * 64 + c];
        v = s;
    }
    g_wcat[k * 192 + j] = v;
}

// ---------------- fused GEMM: [h0 | x_l | x_r] = x @ wcat (+bias on l/r) ----------------
__global__ void k_gemm_pre(const float* __restrict__ x,
                           const float* __restrict__ b_l,
                           const float* __restrict__ b_r) {
    __shared__ float xs[64][33];
    __shared__ __align__(16) float wc[32 * 192];
    int tid = threadIdx.x;
    int node0 = blockIdx.x * 64;
    int tx = tid & 15, ty = tid >> 4;
    int r0 = ty * 4, c0 = tx * 12;

    float acc[4][12];
    #pragma unroll
    for (int i = 0; i < 4; i++)
        #pragma unroll
        for (int j = 0; j < 12; j++) acc[i][j] = 0.f;

    for (int k0 = 0; k0 < 128; k0 += 32) {
        for (int idx = tid; idx < 64 * 32; idx += 256) {
            int r = idx >> 5, c = idx & 31;
            int node = node0 + r;
            xs[r][c] = (node < NN) ? x[node * 128 + k0 + c] : 0.f;
        }
        for (int idx = tid; idx < 32 * 192; idx += 256) {
            int r = idx / 192, c = idx % 192;
            wc[r * 192 + c] = g_wcat[(k0 + r) * 192 + c];
        }
        __syncthreads();
        #pragma unroll
        for (int kk = 0; kk < 32; kk++) {
            float aa[4] = {xs[r0 + 0][kk], xs[r0 + 1][kk],
                           xs[r0 + 2][kk], xs[r0 + 3][kk]};
            const float4* wp = (const float4*)&wc[kk * 192 + c0];
            float4 bv0 = wp[0], bv1 = wp[1], bv2 = wp[2];
            float bb[12] = {bv0.x, bv0.y, bv0.z, bv0.w,
                            bv1.x, bv1.y, bv1.z, bv1.w,
                            bv2.x, bv2.y, bv2.z, bv2.w};
            #pragma unroll
            for (int i = 0; i < 4; i++)
                #pragma unroll
                for (int j = 0; j < 12; j++)
                    acc[i][j] = fmaf(aa[i], bb[j], acc[i][j]);
        }
        __syncthreads();
    }
    #pragma unroll
    for (int i = 0; i < 4; i++) {
        int node = node0 + r0 + i;
        if (node >= NN) continue;
        #pragma unroll
        for (int j = 0; j < 12; j++) {
            int gc = c0 + j;
            float v = acc[i][j];
            if (gc < 64)        g_h0[node * 64 + gc] = v;
            else if (gc < 128)  g_xl[node * 64 + gc - 64]  = v + b_l[gc - 64];
            else                g_xr[node * 64 + gc - 128] = v + b_r[gc - 128];
        }
    }
}

// ---------------- histogram: in-degree + edge-weight sums over dst ----------------
__global__ void k_hist(const void* __restrict__ ei, const float* __restrict__ ew) {
    int e = blockIdx.x * blockDim.x + threadIdx.x;
    if (e >= EE) return;
    int d = load_idx(ei, EE + e);
    atomicAdd(&g_cnt[d], 1);
    atomicAdd(&g_sumw[d], ew[e]);
}

// ---------------- 3-phase exclusive scan of g_cnt -> g_rowptr ----------------
__global__ void k_scan_p1() {
    int base = blockIdx.x * 1024;
    int s = 0;
    #pragma unroll
    for (int j = 0; j < 4; j++) {
        int k = base + threadIdx.x + j * 256;
        if (k < NN) s += g_cnt[k];
    }
    for (int o = 16; o; o >>= 1) s += __shfl_xor_sync(~0u, s, o);
    __shared__ int sh[8];
    if ((threadIdx.x & 31) == 0) sh[threadIdx.x >> 5] = s;
    __syncthreads();
    if (threadIdx.x == 0) {
        int t = 0;
        for (int w = 0; w < 8; w++) t += sh[w];
        g_bsum[blockIdx.x] = t;
    }
}
__global__ void k_scan_p2(int nb) {
    __shared__ int sh[128];
    sh[threadIdx.x] = (threadIdx.x < nb) ? g_bsum[threadIdx.x] : 0;
    __syncthreads();
    if (threadIdx.x == 0) {
        int run = 0;
        for (int b = 0; b < nb; b++) { int t = sh[b]; sh[b] = run; run += t; }
        g_rowptr[NN] = run;
    }
    __syncthreads();
    if (threadIdx.x < nb) g_boff[threadIdx.x] = sh[threadIdx.x];
}
__global__ void k_scan_p3() {
    int base = blockIdx.x * 1024;
    int idx = base + threadIdx.x * 4;
    int v[4];
    #pragma unroll
    for (int j = 0; j < 4; j++) {
        int k = idx + j;
        v[j] = (k < NN) ? g_cnt[k] : 0;
    }
    int s = v[0] + v[1] + v[2] + v[3];
    int lane = threadIdx.x & 31, wid = threadIdx.x >> 5;
    int xval = s;
    for (int o = 1; o < 32; o <<= 1) {
        int y = __shfl_up_sync(~0u, xval, o);
        if (lane >= o) xval += y;
    }
    __shared__ int wsum[8];
    if (lane == 31) wsum[wid] = xval;
    __syncthreads();
    if (wid == 0) {
        int w = (lane < 8) ? wsum[lane] : 0;
        for (int o = 1; o < 8; o <<= 1) {
            int y = __shfl_up_sync(~0u, w, o);
            if (lane >= o) w += y;
        }
        if (lane < 8) wsum[lane] = w;
    }
    __syncthreads();
    int excl = xval - s + (wid > 0 ? wsum[wid - 1] : 0) + g_boff[blockIdx.x];
    #pragma unroll
    for (int j = 0; j < 4; j++) {
        int k = idx + j;
        if (k < NN) g_rowptr[k] = excl;
        excl += v[j];
    }
}

// ---------------- scatter edges into CSR (by dst) ----------------
__global__ void k_scatter(const void* __restrict__ ei, const float* __restrict__ ew) {
    int e = blockIdx.x * blockDim.x + threadIdx.x;
    if (e >= EE) return;
    int d = load_idx(ei, EE + e);
    int s = load_idx(ei, e);
    int pos = g_rowptr[d] + atomicAdd(&g_fill[d], 1);
    g_csr[pos] = make_int2(s, __float_as_int(ew[e]));
}

// ---------------- main edge kernel: warp per node, fused softmax-aggregate + ELU + residual ----------------
__global__ void k_edge(const float* __restrict__ W_edge,
                       const float* __restrict__ att,
                       const float* __restrict__ gat_bias,
                       float* __restrict__ out_h) {
    int warp = (blockIdx.x * blockDim.x + threadIdx.x) >> 5;
    int lane = threadIdx.x & 31;
    if (warp >= NN) return;
    int i = warp;

    const float2* xl2 = (const float2*)g_xl;
    float2 xr = ((const float2*)g_xr)[i * 32 + lane];
    float2 we = ((const float2*)W_edge)[lane];
    float2 at = ((const float2*)att)[lane];

    int start = g_rowptr[i];
    int deg   = g_rowptr[i + 1] - start;
    float ea_self = g_sumw[i] / fmaxf((float)g_cnt[i], 1.0f);

    float den = 0.f, ax = 0.f, ay = 0.f;
    for (int t = 0; t <= deg; t++) {
        int s; float ea;
        if (t < deg) {
            int2 p = g_csr[start + t];
            s = p.x; ea = __int_as_float(p.y);
        } else {
            s = i; ea = ea_self;
        }
        float2 xlv = xl2[s * 32 + lane];
        float fx = fmaf(ea, we.x, xlv.x + xr.x);
        float fy = fmaf(ea, we.y, xlv.y + xr.y);
        fx = fx > 0.f ? fx : 0.2f * fx;
        fy = fy > 0.f ? fy : 0.2f * fy;
        float p = fx * at.x + fy * at.y;
        p += __shfl_xor_sync(~0u, p, 1);
        p += __shfl_xor_sync(~0u, p, 2);
        p += __shfl_xor_sync(~0u, p, 4);
        float ex = __expf(p);
        den += ex;
        ax = fmaf(ex, xlv.x, ax);
        ay = fmaf(ex, xlv.y, ay);
    }
    float inv = 1.0f / den;
    float2 gb = ((const float2*)gat_bias)[lane];
    float ox = fmaf(ax, inv, gb.x);
    float oy = fmaf(ay, inv, gb.y);
    ox = ox > 0.f ? ox : expm1f(ox);   // ELU
    oy = oy > 0.f ? oy : expm1f(oy);
    float2 h0v = ((const float2*)g_h0)[i * 32 + lane];
    ((float2*)out_h)[i * 32 + lane] = make_float2(h0v.x + ox, h0v.y + oy);
}

// ---------------- MLP tail: z = relu(h@W1+b1); logits = z@W2+b2 ----------------
__global__ void k_mlp(const float* __restrict__ h,
                      const float* __restrict__ W1, const float* __restrict__ b1,
                      const float* __restrict__ W2, const float* __restrict__ b2,
                      float* __restrict__ logits) {
    __shared__ float hs[64][65];
    __shared__ __align__(16) float W1s[64 * 64];
    __shared__ float W2s[64 * 10];
    __shared__ float b1s[64];
    __shared__ float b2s[16];
    int tid = threadIdx.x;
    int node0 = blockIdx.x * 64;

    for (int idx = tid; idx < 64 * 64; idx += 256) {
        W1s[idx] = W1[idx];
        int r = idx >> 6, c = idx & 63;
        int node = node0 + r;
        hs[r][c] = (node < NN) ? h[node * 64 + c] : 0.f;
    }
    for (int idx = tid; idx < 640; idx += 256) W2s[idx] = W2[idx];
    if (tid < 64) b1s[tid] = b1[tid];
    if (tid < 10) b2s[tid] = b2[tid];
    __syncthreads();

    int tx = tid & 15, ty = tid >> 4;
    int r0 = ty * 4, c0 = tx * 4;
    float acc[4][4];
    #pragma unroll
    for (int i = 0; i < 4; i++)
        #pragma unroll
        for (int j = 0; j < 4; j++) acc[i][j] = 0.f;
    #pragma unroll 8
    for (int k = 0; k < 64; k++) {
        float a[4] = {hs[r0][k], hs[r0 + 1][k], hs[r0 + 2][k], hs[r0 + 3][k]};
        float4 bv = *(const float4*)&W1s[k * 64 + c0];
        float bb[4] = {bv.x, bv.y, bv.z, bv.w};
        #pragma unroll
        for (int i = 0; i < 4; i++)
            #pragma unroll
            for (int j = 0; j < 4; j++)
                acc[i][j] = fmaf(a[i], bb[j], acc[i][j]);
    }
    __syncthreads();
    #pragma unroll
    for (int i = 0; i < 4; i++)
        #pragma unroll
        for (int j = 0; j < 4; j++)
            hs[r0 + i][c0 + j] = fmaxf(acc[i][j] + b1s[c0 + j], 0.f);
    __syncthreads();

    for (int idx = tid; idx < 640; idx += 256) {
        int r = idx / 10, c = idx % 10;
        float s = b2s[c];
        #pragma unroll 8
        for (int k = 0; k < 64; k++) s += hs[r][k] * W2s[k * 10 + c];
        int node = node0 + r;
        if (node < NN) logits[node * 10 + c] = s;
    }
}

// ---------------- launch ----------------
extern "C" void kernel_launch(void* const* d_in, const int* in_sizes, int n_in,
                              void* d_out, int out_size) {
    const float* x        = (const float*)d_in[0];
    const float* ew       = (const float*)d_in[1];
    const float* W_pre    = (const float*)d_in[2];
    const float* W_l      = (const float*)d_in[3];
    const float* b_l      = (const float*)d_in[4];
    const float* W_r      = (const float*)d_in[5];
    const float* b_r      = (const float*)d_in[6];
    const float* att      = (const float*)d_in[7];
    const float* W_edge   = (const float*)d_in[8];
    const float* gat_bias = (const float*)d_in[9];
    const float* W1       = (const float*)d_in[10];
    const float* b1       = (const float*)d_in[11];
    const float* W2       = (const float*)d_in[12];
    const float* b2       = (const float*)d_in[13];
    const void*  ei       = d_in[14];

    float* out_h      = (float*)d_out;
    float* out_logits = (float*)d_out + (size_t)NN * 64;

    const int NB = (NN + 1023) / 1024;  // 98

    k_detect<<<1, 32>>>((const int*)ei);
    k_zero<<<(NN + 255) / 256, 256>>>();
    k_build_wcat<<<128, 192>>>(W_pre, W_l, W_r);
    k_hist<<<(EE + 255) / 256, 256>>>(ei, ew);
    k_scan_p1<<<NB, 256>>>();
    k_scan_p2<<<1, 128>>>(NB);
    k_scan_p3<<<NB, 256>>>();
    k_scatter<<<(EE + 255) / 256, 256>>>(ei, ew);
    k_gemm_pre<<<(NN + 63) / 64, 256>>>(x, b_l, b_r);
    k_edge<<<(NN * 32 + 255) / 256, 256>>>(W_edge, att, gat_bias, out_h);
    k_mlp<<<(NN + 63) / 64, 256>>>(out_h, W1, b1, W2, b2, out_logits);
}